// round 16
// baseline (speedup 1.0000x reference)
#include <cuda_runtime.h>
#include <math.h>

#define BD  2
#define CD  96
#define HD  64
#define WD  64
#define LD  4096
#define DI  192
#define DS  16
#define HIDN 192
#define NC  64
#define CT  64

// ---------------- scratch (device globals) ----------------
__device__ float g_x1  [(long)BD*CD*LD];
__device__ float g_xn  [(long)BD*LD*CD];
__device__ float g_xz  [2][(long)BD*LD*384];
__device__ float g_xs  [2][(long)BD*LD*DI];
__device__ float g_xdbl[2][(long)BD*LD*38];
__device__ float g_delta[2][(long)BD*LD*DI];
__device__ float g_chH [2][(long)BD*NC*DI*DS];
__device__ float g_chD [2][(long)BD*NC*DI];
__device__ float g_comb [(long)BD*LD*DI];
__device__ float g_comb2[(long)BD*LD*DI];
__device__ float g_xmid[(long)BD*CD*LD];
__device__ float g_xm  [(long)BD*LD*CD];
__device__ float g_hbuf[(long)BD*3*HIDN*LD];
__device__ float g_gg  [(long)BD*HIDN*LD];

#define LOG2E 1.4426950408889634f

// ---------------- helpers ----------------
__device__ __forceinline__ float wsum(float v) {
#pragma unroll
    for (int o = 16; o > 0; o >>= 1) v += __shfl_xor_sync(0xffffffffu, v, o);
    return v;
}
__device__ __forceinline__ unsigned pk(float lo, float hi) {
    unsigned r;
    asm("cvt.rn.bf16x2.f32 %0, %1, %2;" : "=r"(r) : "f"(hi), "f"(lo));
    return r;
}
__device__ __forceinline__ void mma_bf16(float* d, const unsigned* a, const unsigned* b) {
    asm volatile(
        "mma.sync.aligned.m16n8k16.row.col.f32.bf16.bf16.f32 "
        "{%0,%1,%2,%3},{%4,%5,%6,%7},{%8,%9},{%0,%1,%2,%3};"
        : "+f"(d[0]), "+f"(d[1]), "+f"(d[2]), "+f"(d[3])
        : "r"(a[0]), "r"(a[1]), "r"(a[2]), "r"(a[3]), "r"(b[0]), "r"(b[1]));
}

// ============ double LayerNorm (tile = 32 positions, 256 blocks) ============
__global__ void __launch_bounds__(256) ln_double_k(
    const float* __restrict__ x,
    const float* __restrict__ w1, const float* __restrict__ b1,
    const float* __restrict__ w2, const float* __restrict__ b2)
{
    __shared__ float s1[96 * 33];
    const int tid = threadIdx.x;
    const int w = tid >> 5, lane = tid & 31;
    int b = blockIdx.x >> 7, l0 = (blockIdx.x & 127) << 5;
    for (int i = tid; i < 96 * 32; i += 256) {
        int c = i >> 5, l = i & 31;
        s1[c * 33 + l] = x[((long)b * CD + c) * LD + l0 + l];
    }
    __syncthreads();
    for (int j = 0; j < 4; j++) {
        int l = (w << 2) + j;
        float v0 = s1[lane * 33 + l], v1 = s1[(lane + 32) * 33 + l], v2 = s1[(lane + 64) * 33 + l];
        float u = wsum(v0 + v1 + v2) * (1.f / 96.f);
        float q = (v0 - u) * (v0 - u) + (v1 - u) * (v1 - u) + (v2 - u) * (v2 - u);
        q = wsum(q);
        float rs = rsqrtf(q * (1.f / 96.f) + 1e-6f);
        float a0 = w1[lane] * (v0 - u) * rs + b1[lane];
        float a1 = w1[lane + 32] * (v1 - u) * rs + b1[lane + 32];
        float a2 = w1[lane + 64] * (v2 - u) * rs + b1[lane + 64];
        s1[lane * 33 + l] = a0; s1[(lane + 32) * 33 + l] = a1; s1[(lane + 64) * 33 + l] = a2;
        float u2 = wsum(a0 + a1 + a2) * (1.f / 96.f);
        float q2 = (a0 - u2) * (a0 - u2) + (a1 - u2) * (a1 - u2) + (a2 - u2) * (a2 - u2);
        q2 = wsum(q2);
        float rs2 = rsqrtf(q2 * (1.f / 96.f) + 1e-5f);
        float* xnp = g_xn + ((long)b * LD + l0 + l) * CD;
        xnp[lane]      = (a0 - u2) * rs2 * w2[lane]      + b2[lane];
        xnp[lane + 32] = (a1 - u2) * rs2 * w2[lane + 32] + b2[lane + 32];
        xnp[lane + 64] = (a2 - u2) * rs2 * w2[lane + 64] + b2[lane + 64];
    }
    __syncthreads();
    for (int i = tid; i < 96 * 32; i += 256) {
        int c = i >> 5, l = i & 31;
        g_x1[((long)b * CD + c) * LD + l0 + l] = s1[c * 33 + l];
    }
}

// ============ full-K BF16 GEMM: one sync, then KK/16 MMA steps ============
template<int FM, int KK, bool BT, int EPI>
__global__ void __launch_bounds__(256, 3) gemm_fk(
    const float* __restrict__ Abase, const float* __restrict__ B0, const float* __restrict__ B1,
    float* __restrict__ Cbase, int M, int N, long sA, long sB, long sC,
    const float* __restrict__ gmul, const float* __restrict__ residb, long sR)
{
    constexpr int AW = FM * 64 + 8;
    constexpr int KP = KK / 2;
    extern __shared__ unsigned dyn[];
    unsigned* As = dyn;                    // [KP][AW]
    unsigned* Bs = dyn + KP * AW;          // [KP][72]
    const int z = blockIdx.z;
    const float* A = Abase + (long)z * sA;
    const float* B = (z == 1 && B1) ? B1 : B0;
    B += (long)z * sB;
    float* C = Cbase + (long)z * sC;
    const float* resid = residb ? residb + (long)z * sR : nullptr;

    const int tid = threadIdx.x;
    const int m0 = blockIdx.y * (FM * 64), n0 = blockIdx.x << 6;
    const int tr = tid & 63, tk = (tid >> 6) << 2;
    const int wid = tid >> 5, lane = tid & 31;
    const int wm = (wid >> 1) * (FM * 16), wn = (wid & 1) << 5;
    const int gid = lane >> 2, tig = lane & 3;

    float acc[FM][4][4];
#pragma unroll
    for (int f = 0; f < FM; f++)
#pragma unroll
        for (int g = 0; g < 4; g++)
#pragma unroll
            for (int i = 0; i < 4; i++) acc[f][g][i] = 0.f;

#pragma unroll
    for (int k0 = 0; k0 < KK; k0 += 16) {
        const int kp = (k0 + tk) >> 1;
#pragma unroll
        for (int h = 0; h < FM; h++) {
            int m = m0 + tr + (h << 6);
            float4 v = make_float4(0.f, 0.f, 0.f, 0.f);
            if (m < M) v = *(const float4*)(A + (long)m * KK + k0 + tk);
            unsigned* ap = As + kp * AW + tr + (h << 6);
            ap[0 * AW] = pk(v.x, v.y);
            ap[1 * AW] = pk(v.z, v.w);
        }
        if (BT) {
            int n = n0 + tr;
            float4 v = make_float4(0.f, 0.f, 0.f, 0.f);
            if (n < N) v = *(const float4*)(B + (long)n * KK + k0 + tk);
            unsigned* bp = Bs + kp * 72 + tr;
            bp[0 * 72] = pk(v.x, v.y);
            bp[1 * 72] = pk(v.z, v.w);
        } else {
            int n = n0 + tr;
            float v0 = 0.f, v1 = 0.f, v2 = 0.f, v3 = 0.f;
            if (n < N) {
                v0 = B[(long)(k0 + tk + 0) * N + n];
                v1 = B[(long)(k0 + tk + 1) * N + n];
                v2 = B[(long)(k0 + tk + 2) * N + n];
                v3 = B[(long)(k0 + tk + 3) * N + n];
            }
            unsigned* bp = Bs + kp * 72 + tr;
            bp[0 * 72] = pk(v0, v1);
            bp[1 * 72] = pk(v2, v3);
        }
    }
    __syncthreads();

#pragma unroll
    for (int kk = 0; kk < KK / 16; kk++) {
        const int kb = kk << 3;
        unsigned a[FM][4], b[4][2];
#pragma unroll
        for (int f = 0; f < FM; f++) {
            int mb = wm + (f << 4) + gid;
            a[f][0] = As[(kb + tig) * AW + mb];
            a[f][1] = As[(kb + tig) * AW + mb + 8];
            a[f][2] = As[(kb + tig + 4) * AW + mb];
            a[f][3] = As[(kb + tig + 4) * AW + mb + 8];
        }
#pragma unroll
        for (int g = 0; g < 4; g++) {
            int nb = wn + (g << 3) + gid;
            b[g][0] = Bs[(kb + tig) * 72 + nb];
            b[g][1] = Bs[(kb + tig + 4) * 72 + nb];
        }
#pragma unroll
        for (int f = 0; f < FM; f++)
#pragma unroll
            for (int g = 0; g < 4; g++)
                mma_bf16(acc[f][g], a[f], b[g]);
    }

#pragma unroll
    for (int f = 0; f < FM; f++) {
#pragma unroll
        for (int h = 0; h < 2; h++) {
            int m = m0 + wm + (f << 4) + gid + (h << 3);
            if (m >= M) continue;
#pragma unroll
            for (int g = 0; g < 4; g++) {
#pragma unroll
                for (int j = 0; j < 2; j++) {
                    int n = n0 + wn + (g << 3) + (tig << 1) + j;
                    if (n >= N) continue;
                    float v = acc[f][g][(h << 1) + j];
                    if (EPI == 0) C[(long)m * N + n] = v;
                    else          C[(long)m * N + n] = resid[(long)m * N + n] + gmul[m] * v;
                }
            }
        }
    }
}

// ============ x_dbl GEMM (BF16, M-tile 32, K=192) + fused delta; 512 blocks ============
// Warp grid 2x4: wm in {0,16}, wn = (wid&3)*16, 2 n-groups per warp.
// B-frag reads overshoot Bs[96][40] by up to 24 words on the last kp rows
// (columns >= 38 discarded); sdt/sW/sbd tail covers the overshoot.
__global__ void __launch_bounds__(256, 4) xdbl_delta_k(
    const float* __restrict__ Abase, const float* __restrict__ B0, const float* __restrict__ B1,
    float* __restrict__ Cbase, const float* __restrict__ Wdt0, const float* __restrict__ Wdt1,
    const float* __restrict__ bdt0, const float* __restrict__ bdt1,
    float* __restrict__ dOut0, float* __restrict__ dOut1)
{
    extern __shared__ unsigned dyn[];
    unsigned* As = dyn;                    // [96][40]  (M-tile 32 + 8 pad)
    unsigned* Bs = dyn + 96 * 40;          // [96][40]
    float* sdt = (float*)(dyn + 96 * 40 + 96 * 40);   // [32][8]
    float* sW  = sdt + 32 * 8;             // [192*6]
    float* sbd = sW + 192 * 6;             // [192]
    const int N = 38, K = DI;
    const int z = blockIdx.z;
    const float* A = Abase + (long)z * ((long)BD * LD * DI);
    const float* B = z ? B1 : B0;
    float* C = Cbase + (long)z * ((long)BD * LD * 38);
    const float* Wdt = z ? Wdt1 : Wdt0;
    const float* bdt = z ? bdt1 : bdt0;
    float* dOut = z ? dOut1 : dOut0;

    const int tid = threadIdx.x;
    const int m0 = blockIdx.y << 5;        // 32-row tile
    const int wid = tid >> 5, lane = tid & 31;
    const int wm = (wid >> 2) << 4;        // {0,16}
    const int wn = (wid & 3) << 4;         // {0,16,32,48}
    const int gid = lane >> 2, tig = lane & 3;

    for (int i = tid; i < 192 * 6; i += 256) sW[i] = Wdt[i];
    if (tid < 192) sbd[tid] = bdt[tid];

    float acc[2][4];
#pragma unroll
    for (int g = 0; g < 2; g++)
#pragma unroll
        for (int i = 0; i < 4; i++) acc[g][i] = 0.f;

    // A fill: 32 rows x 192 cols; thread = (row = tid&31, k-slot = tid>>5 of 8)
    {
        const int ar = tid & 31;
        const int ak = (tid >> 5) << 2;    // 4 floats per slot, slots stride 32
#pragma unroll
        for (int k0 = 0; k0 < 192; k0 += 32) {
            float4 v = *(const float4*)(A + (long)(m0 + ar) * K + k0 + ak);
            const int kp = (k0 + ak) >> 1;
            unsigned* ap = As + kp * 40 + ar;
            ap[0 * 40] = pk(v.x, v.y);
            ap[1 * 40] = pk(v.z, v.w);
        }
    }
    // B fill: 38 rows x 192 cols (same as before)
    {
        const int tr = tid & 63, tk = (tid >> 6) << 2;
#pragma unroll
        for (int k0 = 0; k0 < 192; k0 += 16) {
            float4 bv = make_float4(0.f, 0.f, 0.f, 0.f);
            if (tr < N) bv = *(const float4*)(B + (long)tr * K + k0 + tk);
            if (tr < 40) {
                const int kp = (k0 + tk) >> 1;
                unsigned* bp = Bs + kp * 40 + tr;
                bp[0 * 40] = pk(bv.x, bv.y);
                bp[1 * 40] = pk(bv.z, bv.w);
            }
        }
    }
    __syncthreads();

#pragma unroll
    for (int kk = 0; kk < 12; kk++) {
        const int kb = kk << 3;
        unsigned a[4], b[2][2];
        int mb = wm + gid;
        a[0] = As[(kb + tig) * 40 + mb];
        a[1] = As[(kb + tig) * 40 + mb + 8];
        a[2] = As[(kb + tig + 4) * 40 + mb];
        a[3] = As[(kb + tig + 4) * 40 + mb + 8];
#pragma unroll
        for (int g = 0; g < 2; g++) {
            int nb = wn + (g << 3) + gid;
            b[g][0] = Bs[(kb + tig) * 40 + nb];
            b[g][1] = Bs[(kb + tig + 4) * 40 + nb];
        }
#pragma unroll
        for (int g = 0; g < 2; g++)
            mma_bf16(acc[g], a, b[g]);
    }

#pragma unroll
    for (int h = 0; h < 2; h++) {
        int rl = wm + gid + (h << 3);
        int m = m0 + rl;
#pragma unroll
        for (int g = 0; g < 2; g++) {
#pragma unroll
            for (int j = 0; j < 2; j++) {
                int n = wn + (g << 3) + (tig << 1) + j;
                if (n >= N) continue;
                float v = acc[g][(h << 1) + j];
                C[(long)m * N + n] = v;
                if (n < 6) sdt[rl * 8 + n] = v;
            }
        }
    }
    __syncthreads();
    for (int i = tid; i < 32 * 192; i += 256) {
        int d = i % 192, r = i / 192;
        const float* dtp = &sdt[r * 8];
        float a = sbd[d];
#pragma unroll
        for (int k = 0; k < 6; k++) a += dtp[k] * sW[d * 6 + k];
        float sp = (a > 20.f) ? a : log1pf(__expf(a));
        dOut[(long)(m0 + r) * DI + d] = sp;
    }
}

// ============ conv + SiLU (SMEM-tiled, both dirs) ============
__global__ void __launch_bounds__(192) conv_silu_k(
    const float* __restrict__ cw0, const float* __restrict__ cb0,
    const float* __restrict__ cw1, const float* __restrict__ cb1)
{
    __shared__ float sX[67 * 200];
    __shared__ float scw[192 * 4];
    __shared__ float scb[192];
    const int tid = threadIdx.x;
    int tile = blockIdx.x & 63;
    int b    = (blockIdx.x >> 6) & 1;
    int dir  = blockIdx.x >> 7;
    int t0 = tile << 6;
    const float* cw = dir ? cw1 : cw0;
    const float* cb = dir ? cb1 : cb0;
    for (int i = tid; i < 192 * 4; i += 192) scw[i] = cw[i];
    if (tid < 192) scb[tid] = cb[tid];
    for (int i = tid; i < 67 * 48; i += 192) {
        int r = i / 48, c4 = (i % 48) << 2;
        int tt = t0 + r - 3;
        float4 v = make_float4(0.f, 0.f, 0.f, 0.f);
        if (tt >= 0) {
            int l = dir ? (LD - 1 - tt) : tt;
            v = *(const float4*)&g_xz[dir][((long)b * LD + l) * 384 + c4];
        }
        *(float4*)&sX[r * 200 + c4] = v;
    }
    __syncthreads();
    int g4 = tid % 48, tg = tid / 48;
    int d0 = g4 << 2;
    float w00 = scw[(d0+0)*4+0], w01 = scw[(d0+0)*4+1], w02 = scw[(d0+0)*4+2], w03 = scw[(d0+0)*4+3];
    float w10 = scw[(d0+1)*4+0], w11 = scw[(d0+1)*4+1], w12 = scw[(d0+1)*4+2], w13 = scw[(d0+1)*4+3];
    float w20 = scw[(d0+2)*4+0], w21 = scw[(d0+2)*4+1], w22 = scw[(d0+2)*4+2], w23 = scw[(d0+2)*4+3];
    float w30 = scw[(d0+3)*4+0], w31 = scw[(d0+3)*4+1], w32 = scw[(d0+3)*4+2], w33 = scw[(d0+3)*4+3];
    float bb0 = scb[d0], bb1 = scb[d0+1], bb2 = scb[d0+2], bb3 = scb[d0+3];
    for (int ii = 0; ii < 16; ii++) {
        int tloc = tg * 16 + ii;
        float4 acc = make_float4(bb0, bb1, bb2, bb3);
        float4 v0 = *(const float4*)&sX[(tloc + 0) * 200 + d0];
        float4 v1 = *(const float4*)&sX[(tloc + 1) * 200 + d0];
        float4 v2 = *(const float4*)&sX[(tloc + 2) * 200 + d0];
        float4 v3 = *(const float4*)&sX[(tloc + 3) * 200 + d0];
        acc.x += w00*v0.x + w01*v1.x + w02*v2.x + w03*v3.x;
        acc.y += w10*v0.y + w11*v1.y + w12*v2.y + w13*v3.y;
        acc.z += w20*v0.z + w21*v1.z + w22*v2.z + w23*v3.z;
        acc.w += w30*v0.w + w31*v1.w + w32*v2.w + w33*v3.w;
        acc.x = acc.x / (1.f + __expf(-acc.x));
        acc.y = acc.y / (1.f + __expf(-acc.y));
        acc.z = acc.z / (1.f + __expf(-acc.z));
        acc.w = acc.w / (1.f + __expf(-acc.w));
        *(float4*)&g_xs[dir][((long)b * LD + t0 + tloc) * DI + d0] = acc;
    }
}

// ============ scan phase 1 (both dirs, 256 blocks) ============
__global__ void __launch_bounds__(192) scan_p1(
    const float* __restrict__ Alog0, const float* __restrict__ Alog1)
{
    __shared__ float sB[CT * 16];
    int vb = blockIdx.x;
    int dir = vb >> 7, r = vb & 127;
    int b = r >> 6, c = r & 63;
    int d = threadIdx.x;
    const float* Alog = dir ? Alog1 : Alog0;
    const float* xd = g_xdbl[dir] + ((long)b * LD + (long)c * CT) * 38;
    for (int i = d; i < CT * 16; i += 192) {
        int t = i >> 4, s = i & 15;
        sB[i] = xd[t * 38 + 6 + s];
    }
    float Ad[16];
#pragma unroll
    for (int s = 0; s < 16; s++) Ad[s] = -__expf(Alog[d * 16 + s]) * LOG2E;
    __syncthreads();
    float h[16];
#pragma unroll
    for (int s = 0; s < 16; s++) h[s] = 0.f;
    float sd = 0.f;
    const float* dp = g_delta[dir] + ((long)b * LD + (long)c * CT) * DI + d;
    const float* xp = g_xs[dir]    + ((long)b * LD + (long)c * CT) * DI + d;
    float dl = dp[0], xv = xp[0];
    for (int t = 0; t < CT; t++) {
        float dln = 0.f, xvn = 0.f;
        if (t + 1 < CT) { dln = dp[(long)(t + 1) * DI]; xvn = xp[(long)(t + 1) * DI]; }
        float u = dl * xv;
        sd += dl;
        const float* bt = &sB[t * 16];
#pragma unroll
        for (int s = 0; s < 16; s++)
            h[s] = exp2f(Ad[s] * dl) * h[s] + u * bt[s];
        dl = dln; xv = xvn;
    }
    float* hp = g_chH[dir] + (((long)b * NC + c) * DI + d) * 16;
#pragma unroll
    for (int s = 0; s < 16; s++) hp[s] = h[s];
    g_chD[dir][((long)b * NC + c) * DI + d] = sd;
}

// ============ scan phase 2: 96 blocks x 128 (8 d-channels per block) ============
__global__ void __launch_bounds__(128) scan_p2(
    const float* __restrict__ Alog0, const float* __restrict__ Alog1)
{
    int b = blockIdx.y, dir = blockIdx.z;
    int tid = threadIdx.x;
    int d = blockIdx.x * 8 + (tid >> 4);
    int s = tid & 15;
    const float* Alog = dir ? Alog1 : Alog0;
    float Ad = -__expf(Alog[d * 16 + s]) * LOG2E;
    float h = 0.f;
    float* chH = g_chH[dir];
    const float* chD = g_chD[dir];
#pragma unroll 4
    for (int c = 0; c < NC; c++) {
        long bi = ((long)b * NC + c) * DI + d;
        float sd = chD[bi];
        float loc = chH[bi * 16 + s];
        chH[bi * 16 + s] = h;
        h = exp2f(Ad * sd) * h + loc;
    }
}

// ============ scan phase 3: both dirs, one launch, two outputs ============
__global__ void __launch_bounds__(192) scan_p3(
    const float* __restrict__ Alog0, const float* __restrict__ Alog1,
    const float* __restrict__ Dp0, const float* __restrict__ Dp1)
{
    __shared__ float sB[CT * 16];
    __shared__ float sC[CT * 16];
    int vb = blockIdx.x;
    int dir = vb >> 7, r = vb & 127;
    int b = r >> 6, c = r & 63;
    int d = threadIdx.x;
    const float* Alog = dir ? Alog1 : Alog0;
    const float* Dp = dir ? Dp1 : Dp0;
    float* outb = dir ? g_comb2 : g_comb;
    const float* xd = g_xdbl[dir] + ((long)b * LD + (long)c * CT) * 38;
    for (int i = d; i < CT * 16; i += 192) {
        int t = i >> 4, s = i & 15;
        sB[i] = xd[t * 38 + 6 + s];
        sC[i] = xd[t * 38 + 22 + s];
    }
    float Ad[16];
#pragma unroll
    for (int s = 0; s < 16; s++) Ad[s] = -__expf(Alog[d * 16 + s]) * LOG2E;
    float Dd = Dp[d];
    __syncthreads();
    const float* hp = g_chH[dir] + (((long)b * NC + c) * DI + d) * 16;
    float h[16];
#pragma unroll
    for (int s = 0; s < 16; s++) h[s] = hp[s];
    const float* dp = g_delta[dir] + ((long)b * LD + (long)c * CT) * DI + d;
    const float* xp = g_xs[dir]    + ((long)b * LD + (long)c * CT) * DI + d;
    float dl = dp[0], xv = xp[0];
    for (int t = 0; t < CT; t++) {
        float dln = 0.f, xvn = 0.f;
        if (t + 1 < CT) { dln = dp[(long)(t + 1) * DI]; xvn = xp[(long)(t + 1) * DI]; }
        float u = dl * xv;
        const float* bt = &sB[t * 16];
        const float* ct = &sC[t * 16];
        float y = 0.f;
#pragma unroll
        for (int s = 0; s < 16; s++) {
            h[s] = exp2f(Ad[s] * dl) * h[s] + u * bt[s];
            y += h[s] * ct[s];
        }
        int tg = c * CT + t;
        int lo = dir ? (LD - 1 - tg) : tg;
        float zv = g_xz[dir][((long)b * LD + lo) * 384 + 192 + d];
        float val = (y + xv * Dd) * (zv / (1.f + __expf(-zv)));
        outb[((long)b * LD + lo) * DI + d] = val;
        dl = dln; xv = xvn;
    }
}

// ============ yo GEMM (BF16, M-tile 32 x N=96) + resid1 + channel-LN fused ============
__global__ void __launch_bounds__(256) yo_ln_k(
    const float* __restrict__ Wout, const float* __restrict__ x,
    const float* __restrict__ gamma1,
    const float* __restrict__ w1, const float* __restrict__ b1)
{
    __shared__ unsigned As[2][8][40];
    __shared__ unsigned Bs[2][8][104];
    __shared__ float sCc[96 * 33];
    __shared__ float sXx[96 * 33];
    __shared__ float sX1[96 * 33];
    const int tid = threadIdx.x;
    const int m0 = blockIdx.x << 5;
    const int b = m0 >> 12, l0 = m0 & 4095;
    const int wid = tid >> 5, lane = tid & 31;
    const int wm = (wid & 1) << 4;
    const int wn = (wid >> 1) * 24;
    const int gid = lane >> 2, tig = lane & 3;

    float acc[3][4];
#pragma unroll
    for (int g = 0; g < 3; g++)
#pragma unroll
        for (int i = 0; i < 4; i++) acc[g][i] = 0.f;

    auto load_tile = [&](int buf, int k0) {
        if (tid < 128) {
            int ar = tid >> 2, ac = (tid & 3) << 2;
            long ai = (long)(m0 + ar) * DI + k0 + ac;
            float4 va = *(const float4*)(g_comb  + ai);
            float4 vb = *(const float4*)(g_comb2 + ai);
            int kp = ac >> 1;
            As[buf][kp + 0][ar] = pk(va.x + vb.x, va.y + vb.y);
            As[buf][kp + 1][ar] = pk(va.z + vb.z, va.w + vb.w);
        }
        for (int i = tid; i < 96 * 4; i += 256) {
            int n = i >> 2, kc = (i & 3) << 2;
            float4 v = *(const float4*)(Wout + (long)n * DI + k0 + kc);
            int kp = kc >> 1;
            Bs[buf][kp + 0][n] = pk(v.x, v.y);
            Bs[buf][kp + 1][n] = pk(v.z, v.w);
        }
    };

    load_tile(0, 0);
    __syncthreads();
    const int nk = DI >> 4;
    for (int t = 0; t < nk; t++) {
        if (t + 1 < nk) load_tile((t + 1) & 1, (t + 1) << 4);
        const int buf = t & 1;
        unsigned a[4], bfr[3][2];
        int mb = wm + gid;
        a[0] = As[buf][tig][mb];
        a[1] = As[buf][tig][mb + 8];
        a[2] = As[buf][tig + 4][mb];
        a[3] = As[buf][tig + 4][mb + 8];
#pragma unroll
        for (int g = 0; g < 3; g++) {
            int nb = wn + (g << 3) + gid;
            bfr[g][0] = Bs[buf][tig][nb];
            bfr[g][1] = Bs[buf][tig + 4][nb];
        }
#pragma unroll
        for (int g = 0; g < 3; g++)
            mma_bf16(acc[g], a, bfr[g]);
        __syncthreads();
    }

#pragma unroll
    for (int g = 0; g < 3; g++) {
#pragma unroll
        for (int h = 0; h < 2; h++) {
#pragma unroll
            for (int j = 0; j < 2; j++) {
                int n = wn + (g << 3) + (tig << 1) + j;
                int ml = wm + gid + (h << 3);
                sCc[n * 33 + ml] = acc[g][(h << 1) + j];
            }
        }
    }
    for (int i = tid; i < 96 * 32; i += 256) {
        int c = i >> 5, l = i & 31;
        long gi = ((long)b * CD + c) * LD + l0 + l;
        sXx[c * 33 + l] = x[gi];
        sX1[c * 33 + l] = g_x1[gi];
    }
    __syncthreads();
    for (int i = tid; i < 96 * 32; i += 256) {
        int c = i >> 5, l = i & 31;
        sCc[c * 33 + l] = sXx[c * 33 + l] + gamma1[c] * (sCc[c * 33 + l] + sX1[c * 33 + l]);
    }
    __syncthreads();
    for (int i = tid; i < 96 * 32; i += 256) {
        int c = i >> 5, l = i & 31;
        g_xmid[((long)b * CD + c) * LD + l0 + l] = sCc[c * 33 + l];
    }
    for (int j = 0; j < 4; j++) {
        int p = (wid << 2) + j;
        float v0 = sCc[lane * 33 + p], v1 = sCc[(lane + 32) * 33 + p], v2 = sCc[(lane + 64) * 33 + p];
        float u = wsum(v0 + v1 + v2) * (1.f / 96.f);
        float q = (v0 - u) * (v0 - u) + (v1 - u) * (v1 - u) + (v2 - u) * (v2 - u);
        q = wsum(q);
        float rs = rsqrtf(q * (1.f / 96.f) + 1e-6f);
        float* xmp = g_xm + ((long)b * LD + l0 + p) * CD;
        xmp[lane]      = w1[lane] * (v0 - u) * rs + b1[lane];
        xmp[lane + 32] = w1[lane + 32] * (v1 - u) * rs + b1[lane + 32];
        xmp[lane + 64] = w1[lane + 64] * (v2 - u) * rs + b1[lane + 64];
    }
}

// ============ MSFF gate (SMEM-tiled per (b, j) plane) ============
__global__ void __launch_bounds__(256) gate_k(
    const float* __restrict__ dw1, const float* __restrict__ dw2, const float* __restrict__ dw3)
{
    __shared__ float s1[64 * 65], s2[64 * 65], s3[64 * 65];
    const int tid = threadIdx.x;
    int b = blockIdx.x / HIDN, j = blockIdx.x % HIDN;
    const float* p1 = g_hbuf + ((long)b * 3 * HIDN + j) * LD;
    const float* p2 = p1 + (long)HIDN * LD;
    const float* p3 = p2 + (long)HIDN * LD;
    for (int i = tid; i < 4096; i += 256) {
        int y = i >> 6, xx = i & 63;
        s1[y * 65 + xx] = p1[i];
        s2[y * 65 + xx] = p2[i];
        s3[y * 65 + xx] = p3[i];
    }
    float w1r[9], w2r[9], w3r[9];
#pragma unroll
    for (int k = 0; k < 9; k++) { w1r[k] = dw1[j * 9 + k]; w2r[k] = dw2[j * 9 + k]; w3r[k] = dw3[j * 9 + k]; }
    __syncthreads();
    float* og = g_gg + ((long)b * HIDN + j) * LD;
    for (int i = tid; i < 4096; i += 256) {
        int y = i >> 6, xx = i & 63;
        float a1 = 0.f, a2 = 0.f, a3 = 0.f;
#pragma unroll
        for (int ky = 0; ky < 3; ky++) {
#pragma unroll
            for (int kx = 0; kx < 3; kx++) {
                int dy = ky - 1, dx = kx - 1;
                int y1 = y + dy, x1 = xx + dx;
                if (y1 >= 0 && y1 < 64 && x1 >= 0 && x1 < 64) a1 += w1r[ky*3+kx] * s1[y1 * 65 + x1];
                int y2 = y + 2*dy, x2 = xx + 2*dx;
                if (y2 >= 0 && y2 < 64 && x2 >= 0 && x2 < 64) a2 += w2r[ky*3+kx] * s2[y2 * 65 + x2];
                int y3 = y + 3*dy, x3 = xx + 3*dx;
                if (y3 >= 0 && y3 < 64 && x3 >= 0 && x3 < 64) a3 += w3r[ky*3+kx] * s3[y3 * 65 + x3];
            }
        }
        float ge = 0.5f * a1 * (1.f + erff(a1 * 0.70710678118654752f));
        og[i] = ge * a2 * a3;
    }
}

// ---------------- host ----------------
extern "C" void kernel_launch(void* const* d_in, const int* in_sizes, int n_in,
                              void* d_out, int out_size)
{
    const float* x      = (const float*)d_in[0];
    const float* gamma1 = (const float*)d_in[1];
    const float* gamma2 = (const float*)d_in[2];
    const float* ln1w   = (const float*)d_in[3];
    const float* ln1b   = (const float*)d_in[4];
    const float* mnw    = (const float*)d_in[5];
    const float* mnb    = (const float*)d_in[6];
    const float* Win[2]   = {(const float*)d_in[7],  (const float*)d_in[15]};
    const float* convw[2] = {(const float*)d_in[8],  (const float*)d_in[16]};
    const float* convb[2] = {(const float*)d_in[9],  (const float*)d_in[17]};
    const float* Wx[2]    = {(const float*)d_in[10], (const float*)d_in[18]};
    const float* Wdt[2]   = {(const float*)d_in[11], (const float*)d_in[19]};
    const float* bdt[2]   = {(const float*)d_in[12], (const float*)d_in[20]};
    const float* Alog[2]  = {(const float*)d_in[13], (const float*)d_in[21]};
    const float* Dp[2]    = {(const float*)d_in[14], (const float*)d_in[22]};
    const float* Wout   = (const float*)d_in[23];
    const float* mwin   = (const float*)d_in[24];
    const float* dw1    = (const float*)d_in[25];
    const float* dw2    = (const float*)d_in[26];
    const float* dw3    = (const float*)d_in[27];
    const float* mwout  = (const float*)d_in[28];
    float* out = (float*)d_out;

    float *p_xn, *p_xz, *p_xs, *p_xdbl, *p_delta, *p_xm, *p_hbuf, *p_gg, *p_xmid;
    cudaGetSymbolAddress((void**)&p_xn,    g_xn);
    cudaGetSymbolAddress((void**)&p_xz,    g_xz);
    cudaGetSymbolAddress((void**)&p_xs,    g_xs);
    cudaGetSymbolAddress((void**)&p_xdbl,  g_xdbl);
    cudaGetSymbolAddress((void**)&p_delta, g_delta);
    cudaGetSymbolAddress((void**)&p_xm,    g_xm);
    cudaGetSymbolAddress((void**)&p_hbuf,  g_hbuf);
    cudaGetSymbolAddress((void**)&p_gg,    g_gg);
    cudaGetSymbolAddress((void**)&p_xmid,  g_xmid);

    const long DIRD = (long)BD * LD * DI;

    const int SM_G96  = (48 * (2 * 64 + 8) + 48 * 72) * 4;   // ~39.9 KB
    const int SM_G192 = (96 * (1 * 64 + 8) + 96 * 72) * 4;   // ~55.3 KB
    const int SM_XDBL = (96 * 40 + 96 * 40) * 4 + (32 * 8 + 192 * 6 + 192) * 4;  // ~37 KB

    cudaFuncSetAttribute((const void*)gemm_fk<2, 96, true, 0>,
                         cudaFuncAttributeMaxDynamicSharedMemorySize, SM_G96);
    cudaFuncSetAttribute((const void*)gemm_fk<1, 192, false, 1>,
                         cudaFuncAttributeMaxDynamicSharedMemorySize, SM_G192);
    cudaFuncSetAttribute((const void*)xdbl_delta_k,
                         cudaFuncAttributeMaxDynamicSharedMemorySize, SM_XDBL);

    // 0. double LN (256 blocks)
    ln_double_k<<<256, 256>>>(x, ln1w, ln1b, mnw, mnb);

    // 1. xz = xn @ Win^T  M=8192 N=384 K=96 (768 blocks)
    gemm_fk<2, 96, true, 0><<<dim3(6, 64, 2), 256, SM_G96>>>(
        p_xn, Win[0], Win[1], p_xz, BD * LD, 384,
        0, 0, (long)BD * LD * 384, nullptr, nullptr, 0);

    // 2. conv + silu (256 blocks)
    conv_silu_k<<<256, 192>>>(convw[0], convb[0], convw[1], convb[1]);

    // 3. x_dbl GEMM + fused delta (512 blocks, M-tile 32)  <-- ncu-profiled slot
    xdbl_delta_k<<<dim3(1, 256, 2), 256, SM_XDBL>>>(
        p_xs, Wx[0], Wx[1], p_xdbl, Wdt[0], Wdt[1], bdt[0], bdt[1],
        p_delta, p_delta + DIRD);

    // 4. scan p1 (256 blocks)
    scan_p1<<<256, 192>>>(Alog[0], Alog[1]);

    // 5. scan p2 (96 blocks x 128)
    scan_p2<<<dim3(24, BD, 2), 128>>>(Alog[0], Alog[1]);

    // 6. scan p3 both dirs (256 blocks)
    scan_p3<<<256, 192>>>(Alog[0], Alog[1], Dp[0], Dp[1]);

    // 7. yo GEMM + resid1 + channel LN fused (256 blocks)
    yo_ln_k<<<256, 256>>>(Wout, x, gamma1, ln1w, ln1b);

    // 8. h = msff_win @ xm^T  M=576 N=4096 K=96 (640 blocks)
    gemm_fk<2, 96, true, 0><<<dim3(64, 5, 2), 256, SM_G96>>>(
        mwin, p_xm, nullptr, p_hbuf, 3 * HIDN, LD,
        0, (long)LD * CD, (long)3 * HIDN * LD, nullptr, nullptr, 0);

    // 9. gated multiscale dwconv (384 blocks)
    gate_k<<<384, 256>>>(dw1, dw2, dw3);

    // 10. out = xmid + gamma2*(msff_wout @ g)  M=96 N=4096 K=192 (256 blocks)
    gemm_fk<1, 192, false, 1><<<dim3(64, 2, 2), 256, SM_G192>>>(
        mwout, p_gg, nullptr, out, CD, LD,
        0, (long)HIDN * LD, (long)CD * LD, gamma2, p_xmid, (long)CD * LD);
}

// round 17
// speedup vs baseline: 1.0301x; 1.0301x over previous
#include <cuda_runtime.h>
#include <math.h>

#define BD  2
#define CD  96
#define HD  64
#define WD  64
#define LD  4096
#define DI  192
#define DS  16
#define HIDN 192
#define NC  64
#define CT  64

// ---------------- scratch (device globals) ----------------
__device__ float g_x1  [(long)BD*CD*LD];
__device__ float g_xn  [(long)BD*LD*CD];
__device__ float g_xz  [2][(long)BD*LD*384];
__device__ float g_xs  [2][(long)BD*LD*DI];
__device__ float g_xdbl[2][(long)BD*LD*38];
__device__ float g_delta[2][(long)BD*LD*DI];
__device__ float g_chH [2][(long)BD*NC*DI*DS];
__device__ float g_chD [2][(long)BD*NC*DI];
__device__ float g_comb [(long)BD*LD*DI];
__device__ float g_comb2[(long)BD*LD*DI];
__device__ float g_xmid[(long)BD*CD*LD];
__device__ float g_xm  [(long)BD*LD*CD];
__device__ float g_hbuf[(long)BD*3*HIDN*LD];
__device__ float g_gg  [(long)BD*HIDN*LD];

#define LOG2E 1.4426950408889634f

// ---------------- helpers ----------------
__device__ __forceinline__ float wsum(float v) {
#pragma unroll
    for (int o = 16; o > 0; o >>= 1) v += __shfl_xor_sync(0xffffffffu, v, o);
    return v;
}
__device__ __forceinline__ unsigned pk(float lo, float hi) {
    unsigned r;
    asm("cvt.rn.bf16x2.f32 %0, %1, %2;" : "=r"(r) : "f"(hi), "f"(lo));
    return r;
}
__device__ __forceinline__ unsigned f2tf(float f) {
    unsigned r;
    asm("cvt.rna.tf32.f32 %0, %1;" : "=r"(r) : "f"(f));
    return r;
}
__device__ __forceinline__ void mma_bf16(float* d, const unsigned* a, const unsigned* b) {
    asm volatile(
        "mma.sync.aligned.m16n8k16.row.col.f32.bf16.bf16.f32 "
        "{%0,%1,%2,%3},{%4,%5,%6,%7},{%8,%9},{%0,%1,%2,%3};"
        : "+f"(d[0]), "+f"(d[1]), "+f"(d[2]), "+f"(d[3])
        : "r"(a[0]), "r"(a[1]), "r"(a[2]), "r"(a[3]), "r"(b[0]), "r"(b[1]));
}
__device__ __forceinline__ void mma_tf32(float* d, const unsigned* a, const unsigned* b) {
    asm volatile(
        "mma.sync.aligned.m16n8k8.row.col.f32.tf32.tf32.f32 "
        "{%0,%1,%2,%3},{%4,%5,%6,%7},{%8,%9},{%0,%1,%2,%3};"
        : "+f"(d[0]), "+f"(d[1]), "+f"(d[2]), "+f"(d[3])
        : "r"(a[0]), "r"(a[1]), "r"(a[2]), "r"(a[3]), "r"(b[0]), "r"(b[1]));
}

// ============ double LayerNorm (tile = 32 positions, 256 blocks) ============
__global__ void __launch_bounds__(256) ln_double_k(
    const float* __restrict__ x,
    const float* __restrict__ w1, const float* __restrict__ b1,
    const float* __restrict__ w2, const float* __restrict__ b2)
{
    __shared__ float s1[96 * 33];
    const int tid = threadIdx.x;
    const int w = tid >> 5, lane = tid & 31;
    int b = blockIdx.x >> 7, l0 = (blockIdx.x & 127) << 5;
    for (int i = tid; i < 96 * 32; i += 256) {
        int c = i >> 5, l = i & 31;
        s1[c * 33 + l] = x[((long)b * CD + c) * LD + l0 + l];
    }
    __syncthreads();
    for (int j = 0; j < 4; j++) {
        int l = (w << 2) + j;
        float v0 = s1[lane * 33 + l], v1 = s1[(lane + 32) * 33 + l], v2 = s1[(lane + 64) * 33 + l];
        float u = wsum(v0 + v1 + v2) * (1.f / 96.f);
        float q = (v0 - u) * (v0 - u) + (v1 - u) * (v1 - u) + (v2 - u) * (v2 - u);
        q = wsum(q);
        float rs = rsqrtf(q * (1.f / 96.f) + 1e-6f);
        float a0 = w1[lane] * (v0 - u) * rs + b1[lane];
        float a1 = w1[lane + 32] * (v1 - u) * rs + b1[lane + 32];
        float a2 = w1[lane + 64] * (v2 - u) * rs + b1[lane + 64];
        s1[lane * 33 + l] = a0; s1[(lane + 32) * 33 + l] = a1; s1[(lane + 64) * 33 + l] = a2;
        float u2 = wsum(a0 + a1 + a2) * (1.f / 96.f);
        float q2 = (a0 - u2) * (a0 - u2) + (a1 - u2) * (a1 - u2) + (a2 - u2) * (a2 - u2);
        q2 = wsum(q2);
        float rs2 = rsqrtf(q2 * (1.f / 96.f) + 1e-5f);
        float* xnp = g_xn + ((long)b * LD + l0 + l) * CD;
        xnp[lane]      = (a0 - u2) * rs2 * w2[lane]      + b2[lane];
        xnp[lane + 32] = (a1 - u2) * rs2 * w2[lane + 32] + b2[lane + 32];
        xnp[lane + 64] = (a2 - u2) * rs2 * w2[lane + 64] + b2[lane + 64];
    }
    __syncthreads();
    for (int i = tid; i < 96 * 32; i += 256) {
        int c = i >> 5, l = i & 31;
        g_x1[((long)b * CD + c) * LD + l0 + l] = s1[c * 33 + l];
    }
}

// ============ full-K BF16 GEMM: one sync, then KK/16 MMA steps ============
template<int FM, int KK, bool BT, int EPI>
__global__ void __launch_bounds__(256, 3) gemm_fk(
    const float* __restrict__ Abase, const float* __restrict__ B0, const float* __restrict__ B1,
    float* __restrict__ Cbase, int M, int N, long sA, long sB, long sC,
    const float* __restrict__ gmul, const float* __restrict__ residb, long sR)
{
    constexpr int AW = FM * 64 + 8;
    constexpr int KP = KK / 2;
    extern __shared__ unsigned dyn[];
    unsigned* As = dyn;                    // [KP][AW]
    unsigned* Bs = dyn + KP * AW;          // [KP][72]
    const int z = blockIdx.z;
    const float* A = Abase + (long)z * sA;
    const float* B = (z == 1 && B1) ? B1 : B0;
    B += (long)z * sB;
    float* C = Cbase + (long)z * sC;
    const float* resid = residb ? residb + (long)z * sR : nullptr;

    const int tid = threadIdx.x;
    const int m0 = blockIdx.y * (FM * 64), n0 = blockIdx.x << 6;
    const int tr = tid & 63, tk = (tid >> 6) << 2;
    const int wid = tid >> 5, lane = tid & 31;
    const int wm = (wid >> 1) * (FM * 16), wn = (wid & 1) << 5;
    const int gid = lane >> 2, tig = lane & 3;

    float acc[FM][4][4];
#pragma unroll
    for (int f = 0; f < FM; f++)
#pragma unroll
        for (int g = 0; g < 4; g++)
#pragma unroll
            for (int i = 0; i < 4; i++) acc[f][g][i] = 0.f;

#pragma unroll
    for (int k0 = 0; k0 < KK; k0 += 16) {
        const int kp = (k0 + tk) >> 1;
#pragma unroll
        for (int h = 0; h < FM; h++) {
            int m = m0 + tr + (h << 6);
            float4 v = make_float4(0.f, 0.f, 0.f, 0.f);
            if (m < M) v = *(const float4*)(A + (long)m * KK + k0 + tk);
            unsigned* ap = As + kp * AW + tr + (h << 6);
            ap[0 * AW] = pk(v.x, v.y);
            ap[1 * AW] = pk(v.z, v.w);
        }
        if (BT) {
            int n = n0 + tr;
            float4 v = make_float4(0.f, 0.f, 0.f, 0.f);
            if (n < N) v = *(const float4*)(B + (long)n * KK + k0 + tk);
            unsigned* bp = Bs + kp * 72 + tr;
            bp[0 * 72] = pk(v.x, v.y);
            bp[1 * 72] = pk(v.z, v.w);
        } else {
            int n = n0 + tr;
            float v0 = 0.f, v1 = 0.f, v2 = 0.f, v3 = 0.f;
            if (n < N) {
                v0 = B[(long)(k0 + tk + 0) * N + n];
                v1 = B[(long)(k0 + tk + 1) * N + n];
                v2 = B[(long)(k0 + tk + 2) * N + n];
                v3 = B[(long)(k0 + tk + 3) * N + n];
            }
            unsigned* bp = Bs + kp * 72 + tr;
            bp[0 * 72] = pk(v0, v1);
            bp[1 * 72] = pk(v2, v3);
        }
    }
    __syncthreads();

#pragma unroll
    for (int kk = 0; kk < KK / 16; kk++) {
        const int kb = kk << 3;
        unsigned a[FM][4], b[4][2];
#pragma unroll
        for (int f = 0; f < FM; f++) {
            int mb = wm + (f << 4) + gid;
            a[f][0] = As[(kb + tig) * AW + mb];
            a[f][1] = As[(kb + tig) * AW + mb + 8];
            a[f][2] = As[(kb + tig + 4) * AW + mb];
            a[f][3] = As[(kb + tig + 4) * AW + mb + 8];
        }
#pragma unroll
        for (int g = 0; g < 4; g++) {
            int nb = wn + (g << 3) + gid;
            b[g][0] = Bs[(kb + tig) * 72 + nb];
            b[g][1] = Bs[(kb + tig + 4) * 72 + nb];
        }
#pragma unroll
        for (int f = 0; f < FM; f++)
#pragma unroll
            for (int g = 0; g < 4; g++)
                mma_bf16(acc[f][g], a[f], b[g]);
    }

#pragma unroll
    for (int f = 0; f < FM; f++) {
#pragma unroll
        for (int h = 0; h < 2; h++) {
            int m = m0 + wm + (f << 4) + gid + (h << 3);
            if (m >= M) continue;
#pragma unroll
            for (int g = 0; g < 4; g++) {
#pragma unroll
                for (int j = 0; j < 2; j++) {
                    int n = n0 + wn + (g << 3) + (tig << 1) + j;
                    if (n >= N) continue;
                    float v = acc[f][g][(h << 1) + j];
                    if (EPI == 0) C[(long)m * N + n] = v;
                    else          C[(long)m * N + n] = resid[(long)m * N + n] + gmul[m] * v;
                }
            }
        }
    }
}

// ============ x_dbl GEMM full-K TF32 (M-tile 64, K=192) + fused delta ============
// (proven-best variant: 24.4 us) B-frag reads overshoot Bs[192][40] by up to
// 24 words (cols >= 38 discarded); sdt/sW/sbd tail covers the overshoot.
__global__ void __launch_bounds__(256, 2) xdbl_delta_k(
    const float* __restrict__ Abase, const float* __restrict__ B0, const float* __restrict__ B1,
    float* __restrict__ Cbase, const float* __restrict__ Wdt0, const float* __restrict__ Wdt1,
    const float* __restrict__ bdt0, const float* __restrict__ bdt1,
    float* __restrict__ dOut0, float* __restrict__ dOut1)
{
    extern __shared__ unsigned dyn[];
    unsigned* As = dyn;                    // [192][72]
    unsigned* Bs = dyn + 192 * 72;         // [192][40]
    float* sdt = (float*)(dyn + 192 * 72 + 192 * 40);   // [64][8]
    float* sW  = sdt + 64 * 8;             // [192*6]
    float* sbd = sW + 192 * 6;             // [192]
    const int N = 38, K = DI;
    const int z = blockIdx.z;
    const float* A = Abase + (long)z * ((long)BD * LD * DI);
    const float* B = z ? B1 : B0;
    float* C = Cbase + (long)z * ((long)BD * LD * 38);
    const float* Wdt = z ? Wdt1 : Wdt0;
    const float* bdt = z ? bdt1 : bdt0;
    float* dOut = z ? dOut1 : dOut0;

    const int tid = threadIdx.x;
    const int m0 = blockIdx.y << 6;
    const int tr = tid & 63, tk = (tid >> 6) << 2;
    const int wid = tid >> 5, lane = tid & 31;
    const int wm = (wid >> 1) << 4, wn = (wid & 1) << 5;
    const int gid = lane >> 2, tig = lane & 3;

    for (int i = tid; i < 192 * 6; i += 256) sW[i] = Wdt[i];
    if (tid < 192) sbd[tid] = bdt[tid];

    float acc[4][4];
#pragma unroll
    for (int g = 0; g < 4; g++)
#pragma unroll
        for (int i = 0; i < 4; i++) acc[g][i] = 0.f;

#pragma unroll
    for (int k0 = 0; k0 < 192; k0 += 16) {
        float4 v = *(const float4*)(A + (long)(m0 + tr) * K + k0 + tk);
        unsigned* ap = As + (k0 + tk) * 72 + tr;
        ap[0 * 72] = f2tf(v.x); ap[1 * 72] = f2tf(v.y);
        ap[2 * 72] = f2tf(v.z); ap[3 * 72] = f2tf(v.w);
        float4 bv = make_float4(0.f, 0.f, 0.f, 0.f);
        if (tr < N) bv = *(const float4*)(B + (long)tr * K + k0 + tk);
        unsigned* bp = Bs + (k0 + tk) * 40 + tr;
        if (tr < 40) {
            bp[0 * 40] = f2tf(bv.x); bp[1 * 40] = f2tf(bv.y);
            bp[2 * 40] = f2tf(bv.z); bp[3 * 40] = f2tf(bv.w);
        }
    }
    __syncthreads();

#pragma unroll
    for (int kk = 0; kk < 24; kk++) {
        const int kb = kk << 3;
        unsigned a[4], b[4][2];
        int mb = wm + gid;
        a[0] = As[(kb + tig) * 72 + mb];
        a[1] = As[(kb + tig) * 72 + mb + 8];
        a[2] = As[(kb + tig + 4) * 72 + mb];
        a[3] = As[(kb + tig + 4) * 72 + mb + 8];
#pragma unroll
        for (int g = 0; g < 4; g++) {
            int nb = wn + (g << 3) + gid;
            b[g][0] = Bs[(kb + tig) * 40 + nb];
            b[g][1] = Bs[(kb + tig + 4) * 40 + nb];
        }
#pragma unroll
        for (int g = 0; g < 4; g++)
            mma_tf32(acc[g], a, b[g]);
    }

#pragma unroll
    for (int h = 0; h < 2; h++) {
        int rl = wm + gid + (h << 3);
        int m = m0 + rl;
#pragma unroll
        for (int g = 0; g < 4; g++) {
#pragma unroll
            for (int j = 0; j < 2; j++) {
                int n = wn + (g << 3) + (tig << 1) + j;
                if (n >= N) continue;
                float v = acc[g][(h << 1) + j];
                C[(long)m * N + n] = v;
                if (n < 6) sdt[rl * 8 + n] = v;
            }
        }
    }
    __syncthreads();
    for (int i = tid; i < 64 * 192; i += 256) {
        int d = i % 192, r = i / 192;
        const float* dtp = &sdt[r * 8];
        float a = sbd[d];
#pragma unroll
        for (int k = 0; k < 6; k++) a += dtp[k] * sW[d * 6 + k];
        float sp = (a > 20.f) ? a : log1pf(__expf(a));
        dOut[(long)(m0 + r) * DI + d] = sp;
    }
}

// ============ conv + SiLU (SMEM-tiled, both dirs) ============
__global__ void __launch_bounds__(192) conv_silu_k(
    const float* __restrict__ cw0, const float* __restrict__ cb0,
    const float* __restrict__ cw1, const float* __restrict__ cb1)
{
    __shared__ float sX[67 * 200];
    __shared__ float scw[192 * 4];
    __shared__ float scb[192];
    const int tid = threadIdx.x;
    int tile = blockIdx.x & 63;
    int b    = (blockIdx.x >> 6) & 1;
    int dir  = blockIdx.x >> 7;
    int t0 = tile << 6;
    const float* cw = dir ? cw1 : cw0;
    const float* cb = dir ? cb1 : cb0;
    for (int i = tid; i < 192 * 4; i += 192) scw[i] = cw[i];
    if (tid < 192) scb[tid] = cb[tid];
    for (int i = tid; i < 67 * 48; i += 192) {
        int r = i / 48, c4 = (i % 48) << 2;
        int tt = t0 + r - 3;
        float4 v = make_float4(0.f, 0.f, 0.f, 0.f);
        if (tt >= 0) {
            int l = dir ? (LD - 1 - tt) : tt;
            v = *(const float4*)&g_xz[dir][((long)b * LD + l) * 384 + c4];
        }
        *(float4*)&sX[r * 200 + c4] = v;
    }
    __syncthreads();
    int g4 = tid % 48, tg = tid / 48;
    int d0 = g4 << 2;
    float w00 = scw[(d0+0)*4+0], w01 = scw[(d0+0)*4+1], w02 = scw[(d0+0)*4+2], w03 = scw[(d0+0)*4+3];
    float w10 = scw[(d0+1)*4+0], w11 = scw[(d0+1)*4+1], w12 = scw[(d0+1)*4+2], w13 = scw[(d0+1)*4+3];
    float w20 = scw[(d0+2)*4+0], w21 = scw[(d0+2)*4+1], w22 = scw[(d0+2)*4+2], w23 = scw[(d0+2)*4+3];
    float w30 = scw[(d0+3)*4+0], w31 = scw[(d0+3)*4+1], w32 = scw[(d0+3)*4+2], w33 = scw[(d0+3)*4+3];
    float bb0 = scb[d0], bb1 = scb[d0+1], bb2 = scb[d0+2], bb3 = scb[d0+3];
    for (int ii = 0; ii < 16; ii++) {
        int tloc = tg * 16 + ii;
        float4 acc = make_float4(bb0, bb1, bb2, bb3);
        float4 v0 = *(const float4*)&sX[(tloc + 0) * 200 + d0];
        float4 v1 = *(const float4*)&sX[(tloc + 1) * 200 + d0];
        float4 v2 = *(const float4*)&sX[(tloc + 2) * 200 + d0];
        float4 v3 = *(const float4*)&sX[(tloc + 3) * 200 + d0];
        acc.x += w00*v0.x + w01*v1.x + w02*v2.x + w03*v3.x;
        acc.y += w10*v0.y + w11*v1.y + w12*v2.y + w13*v3.y;
        acc.z += w20*v0.z + w21*v1.z + w22*v2.z + w23*v3.z;
        acc.w += w30*v0.w + w31*v1.w + w32*v2.w + w33*v3.w;
        acc.x = acc.x / (1.f + __expf(-acc.x));
        acc.y = acc.y / (1.f + __expf(-acc.y));
        acc.z = acc.z / (1.f + __expf(-acc.z));
        acc.w = acc.w / (1.f + __expf(-acc.w));
        *(float4*)&g_xs[dir][((long)b * LD + t0 + tloc) * DI + d0] = acc;
    }
}

// ============ scan phase 1 (both dirs, 256 blocks) ============
__global__ void __launch_bounds__(192) scan_p1(
    const float* __restrict__ Alog0, const float* __restrict__ Alog1)
{
    __shared__ float sB[CT * 16];
    int vb = blockIdx.x;
    int dir = vb >> 7, r = vb & 127;
    int b = r >> 6, c = r & 63;
    int d = threadIdx.x;
    const float* Alog = dir ? Alog1 : Alog0;
    const float* xd = g_xdbl[dir] + ((long)b * LD + (long)c * CT) * 38;
    for (int i = d; i < CT * 16; i += 192) {
        int t = i >> 4, s = i & 15;
        sB[i] = xd[t * 38 + 6 + s];
    }
    float Ad[16];
#pragma unroll
    for (int s = 0; s < 16; s++) Ad[s] = -__expf(Alog[d * 16 + s]) * LOG2E;
    __syncthreads();
    float h[16];
#pragma unroll
    for (int s = 0; s < 16; s++) h[s] = 0.f;
    float sd = 0.f;
    const float* dp = g_delta[dir] + ((long)b * LD + (long)c * CT) * DI + d;
    const float* xp = g_xs[dir]    + ((long)b * LD + (long)c * CT) * DI + d;
    float dl = dp[0], xv = xp[0];
    for (int t = 0; t < CT; t++) {
        float dln = 0.f, xvn = 0.f;
        if (t + 1 < CT) { dln = dp[(long)(t + 1) * DI]; xvn = xp[(long)(t + 1) * DI]; }
        float u = dl * xv;
        sd += dl;
        const float* bt = &sB[t * 16];
#pragma unroll
        for (int s = 0; s < 16; s++)
            h[s] = exp2f(Ad[s] * dl) * h[s] + u * bt[s];
        dl = dln; xv = xvn;
    }
    float* hp = g_chH[dir] + (((long)b * NC + c) * DI + d) * 16;
#pragma unroll
    for (int s = 0; s < 16; s++) hp[s] = h[s];
    g_chD[dir][((long)b * NC + c) * DI + d] = sd;
}

// ============ scan phase 2: 96 blocks x 128 (8 d-channels per block) ============
__global__ void __launch_bounds__(128) scan_p2(
    const float* __restrict__ Alog0, const float* __restrict__ Alog1)
{
    int b = blockIdx.y, dir = blockIdx.z;
    int tid = threadIdx.x;
    int d = blockIdx.x * 8 + (tid >> 4);
    int s = tid & 15;
    const float* Alog = dir ? Alog1 : Alog0;
    float Ad = -__expf(Alog[d * 16 + s]) * LOG2E;
    float h = 0.f;
    float* chH = g_chH[dir];
    const float* chD = g_chD[dir];
#pragma unroll 4
    for (int c = 0; c < NC; c++) {
        long bi = ((long)b * NC + c) * DI + d;
        float sd = chD[bi];
        float loc = chH[bi * 16 + s];
        chH[bi * 16 + s] = h;
        h = exp2f(Ad * sd) * h + loc;
    }
}

// ============ scan phase 3: both dirs, one launch, two outputs ============
__global__ void __launch_bounds__(192) scan_p3(
    const float* __restrict__ Alog0, const float* __restrict__ Alog1,
    const float* __restrict__ Dp0, const float* __restrict__ Dp1)
{
    __shared__ float sB[CT * 16];
    __shared__ float sC[CT * 16];
    int vb = blockIdx.x;
    int dir = vb >> 7, r = vb & 127;
    int b = r >> 6, c = r & 63;
    int d = threadIdx.x;
    const float* Alog = dir ? Alog1 : Alog0;
    const float* Dp = dir ? Dp1 : Dp0;
    float* outb = dir ? g_comb2 : g_comb;
    const float* xd = g_xdbl[dir] + ((long)b * LD + (long)c * CT) * 38;
    for (int i = d; i < CT * 16; i += 192) {
        int t = i >> 4, s = i & 15;
        sB[i] = xd[t * 38 + 6 + s];
        sC[i] = xd[t * 38 + 22 + s];
    }
    float Ad[16];
#pragma unroll
    for (int s = 0; s < 16; s++) Ad[s] = -__expf(Alog[d * 16 + s]) * LOG2E;
    float Dd = Dp[d];
    __syncthreads();
    const float* hp = g_chH[dir] + (((long)b * NC + c) * DI + d) * 16;
    float h[16];
#pragma unroll
    for (int s = 0; s < 16; s++) h[s] = hp[s];
    const float* dp = g_delta[dir] + ((long)b * LD + (long)c * CT) * DI + d;
    const float* xp = g_xs[dir]    + ((long)b * LD + (long)c * CT) * DI + d;
    float dl = dp[0], xv = xp[0];
    for (int t = 0; t < CT; t++) {
        float dln = 0.f, xvn = 0.f;
        if (t + 1 < CT) { dln = dp[(long)(t + 1) * DI]; xvn = xp[(long)(t + 1) * DI]; }
        float u = dl * xv;
        const float* bt = &sB[t * 16];
        const float* ct = &sC[t * 16];
        float y = 0.f;
#pragma unroll
        for (int s = 0; s < 16; s++) {
            h[s] = exp2f(Ad[s] * dl) * h[s] + u * bt[s];
            y += h[s] * ct[s];
        }
        int tg = c * CT + t;
        int lo = dir ? (LD - 1 - tg) : tg;
        float zv = g_xz[dir][((long)b * LD + lo) * 384 + 192 + d];
        float val = (y + xv * Dd) * (zv / (1.f + __expf(-zv)));
        outb[((long)b * LD + lo) * DI + d] = val;
        dl = dln; xv = xvn;
    }
}

// ============ yo GEMM (BF16, M-tile 32 x N=96) + resid1 + channel-LN fused ============
__global__ void __launch_bounds__(256) yo_ln_k(
    const float* __restrict__ Wout, const float* __restrict__ x,
    const float* __restrict__ gamma1,
    const float* __restrict__ w1, const float* __restrict__ b1)
{
    __shared__ unsigned As[2][8][40];
    __shared__ unsigned Bs[2][8][104];
    __shared__ float sCc[96 * 33];
    __shared__ float sXx[96 * 33];
    __shared__ float sX1[96 * 33];
    const int tid = threadIdx.x;
    const int m0 = blockIdx.x << 5;
    const int b = m0 >> 12, l0 = m0 & 4095;
    const int wid = tid >> 5, lane = tid & 31;
    const int wm = (wid & 1) << 4;
    const int wn = (wid >> 1) * 24;
    const int gid = lane >> 2, tig = lane & 3;

    float acc[3][4];
#pragma unroll
    for (int g = 0; g < 3; g++)
#pragma unroll
        for (int i = 0; i < 4; i++) acc[g][i] = 0.f;

    auto load_tile = [&](int buf, int k0) {
        if (tid < 128) {
            int ar = tid >> 2, ac = (tid & 3) << 2;
            long ai = (long)(m0 + ar) * DI + k0 + ac;
            float4 va = *(const float4*)(g_comb  + ai);
            float4 vb = *(const float4*)(g_comb2 + ai);
            int kp = ac >> 1;
            As[buf][kp + 0][ar] = pk(va.x + vb.x, va.y + vb.y);
            As[buf][kp + 1][ar] = pk(va.z + vb.z, va.w + vb.w);
        }
        for (int i = tid; i < 96 * 4; i += 256) {
            int n = i >> 2, kc = (i & 3) << 2;
            float4 v = *(const float4*)(Wout + (long)n * DI + k0 + kc);
            int kp = kc >> 1;
            Bs[buf][kp + 0][n] = pk(v.x, v.y);
            Bs[buf][kp + 1][n] = pk(v.z, v.w);
        }
    };

    load_tile(0, 0);
    __syncthreads();
    const int nk = DI >> 4;
    for (int t = 0; t < nk; t++) {
        if (t + 1 < nk) load_tile((t + 1) & 1, (t + 1) << 4);
        const int buf = t & 1;
        unsigned a[4], bfr[3][2];
        int mb = wm + gid;
        a[0] = As[buf][tig][mb];
        a[1] = As[buf][tig][mb + 8];
        a[2] = As[buf][tig + 4][mb];
        a[3] = As[buf][tig + 4][mb + 8];
#pragma unroll
        for (int g = 0; g < 3; g++) {
            int nb = wn + (g << 3) + gid;
            bfr[g][0] = Bs[buf][tig][nb];
            bfr[g][1] = Bs[buf][tig + 4][nb];
        }
#pragma unroll
        for (int g = 0; g < 3; g++)
            mma_bf16(acc[g], a, bfr[g]);
        __syncthreads();
    }

#pragma unroll
    for (int g = 0; g < 3; g++) {
#pragma unroll
        for (int h = 0; h < 2; h++) {
#pragma unroll
            for (int j = 0; j < 2; j++) {
                int n = wn + (g << 3) + (tig << 1) + j;
                int ml = wm + gid + (h << 3);
                sCc[n * 33 + ml] = acc[g][(h << 1) + j];
            }
        }
    }
    for (int i = tid; i < 96 * 32; i += 256) {
        int c = i >> 5, l = i & 31;
        long gi = ((long)b * CD + c) * LD + l0 + l;
        sXx[c * 33 + l] = x[gi];
        sX1[c * 33 + l] = g_x1[gi];
    }
    __syncthreads();
    for (int i = tid; i < 96 * 32; i += 256) {
        int c = i >> 5, l = i & 31;
        sCc[c * 33 + l] = sXx[c * 33 + l] + gamma1[c] * (sCc[c * 33 + l] + sX1[c * 33 + l]);
    }
    __syncthreads();
    for (int i = tid; i < 96 * 32; i += 256) {
        int c = i >> 5, l = i & 31;
        g_xmid[((long)b * CD + c) * LD + l0 + l] = sCc[c * 33 + l];
    }
    for (int j = 0; j < 4; j++) {
        int p = (wid << 2) + j;
        float v0 = sCc[lane * 33 + p], v1 = sCc[(lane + 32) * 33 + p], v2 = sCc[(lane + 64) * 33 + p];
        float u = wsum(v0 + v1 + v2) * (1.f / 96.f);
        float q = (v0 - u) * (v0 - u) + (v1 - u) * (v1 - u) + (v2 - u) * (v2 - u);
        q = wsum(q);
        float rs = rsqrtf(q * (1.f / 96.f) + 1e-6f);
        float* xmp = g_xm + ((long)b * LD + l0 + p) * CD;
        xmp[lane]      = w1[lane] * (v0 - u) * rs + b1[lane];
        xmp[lane + 32] = w1[lane + 32] * (v1 - u) * rs + b1[lane + 32];
        xmp[lane + 64] = w1[lane + 64] * (v2 - u) * rs + b1[lane + 64];
    }
}

// ============ MSFF gate (SMEM-tiled per (b, j) plane) ============
__global__ void __launch_bounds__(256) gate_k(
    const float* __restrict__ dw1, const float* __restrict__ dw2, const float* __restrict__ dw3)
{
    __shared__ float s1[64 * 65], s2[64 * 65], s3[64 * 65];
    const int tid = threadIdx.x;
    int b = blockIdx.x / HIDN, j = blockIdx.x % HIDN;
    const float* p1 = g_hbuf + ((long)b * 3 * HIDN + j) * LD;
    const float* p2 = p1 + (long)HIDN * LD;
    const float* p3 = p2 + (long)HIDN * LD;
    for (int i = tid; i < 4096; i += 256) {
        int y = i >> 6, xx = i & 63;
        s1[y * 65 + xx] = p1[i];
        s2[y * 65 + xx] = p2[i];
        s3[y * 65 + xx] = p3[i];
    }
    float w1r[9], w2r[9], w3r[9];
#pragma unroll
    for (int k = 0; k < 9; k++) { w1r[k] = dw1[j * 9 + k]; w2r[k] = dw2[j * 9 + k]; w3r[k] = dw3[j * 9 + k]; }
    __syncthreads();
    float* og = g_gg + ((long)b * HIDN + j) * LD;
    for (int i = tid; i < 4096; i += 256) {
        int y = i >> 6, xx = i & 63;
        float a1 = 0.f, a2 = 0.f, a3 = 0.f;
#pragma unroll
        for (int ky = 0; ky < 3; ky++) {
#pragma unroll
            for (int kx = 0; kx < 3; kx++) {
                int dy = ky - 1, dx = kx - 1;
                int y1 = y + dy, x1 = xx + dx;
                if (y1 >= 0 && y1 < 64 && x1 >= 0 && x1 < 64) a1 += w1r[ky*3+kx] * s1[y1 * 65 + x1];
                int y2 = y + 2*dy, x2 = xx + 2*dx;
                if (y2 >= 0 && y2 < 64 && x2 >= 0 && x2 < 64) a2 += w2r[ky*3+kx] * s2[y2 * 65 + x2];
                int y3 = y + 3*dy, x3 = xx + 3*dx;
                if (y3 >= 0 && y3 < 64 && x3 >= 0 && x3 < 64) a3 += w3r[ky*3+kx] * s3[y3 * 65 + x3];
            }
        }
        float ge = 0.5f * a1 * (1.f + erff(a1 * 0.70710678118654752f));
        og[i] = ge * a2 * a3;
    }
}

// ---------------- host ----------------
extern "C" void kernel_launch(void* const* d_in, const int* in_sizes, int n_in,
                              void* d_out, int out_size)
{
    const float* x      = (const float*)d_in[0];
    const float* gamma1 = (const float*)d_in[1];
    const float* gamma2 = (const float*)d_in[2];
    const float* ln1w   = (const float*)d_in[3];
    const float* ln1b   = (const float*)d_in[4];
    const float* mnw    = (const float*)d_in[5];
    const float* mnb    = (const float*)d_in[6];
    const float* Win[2]   = {(const float*)d_in[7],  (const float*)d_in[15]};
    const float* convw[2] = {(const float*)d_in[8],  (const float*)d_in[16]};
    const float* convb[2] = {(const float*)d_in[9],  (const float*)d_in[17]};
    const float* Wx[2]    = {(const float*)d_in[10], (const float*)d_in[18]};
    const float* Wdt[2]   = {(const float*)d_in[11], (const float*)d_in[19]};
    const float* bdt[2]   = {(const float*)d_in[12], (const float*)d_in[20]};
    const float* Alog[2]  = {(const float*)d_in[13], (const float*)d_in[21]};
    const float* Dp[2]    = {(const float*)d_in[14], (const float*)d_in[22]};
    const float* Wout   = (const float*)d_in[23];
    const float* mwin   = (const float*)d_in[24];
    const float* dw1    = (const float*)d_in[25];
    const float* dw2    = (const float*)d_in[26];
    const float* dw3    = (const float*)d_in[27];
    const float* mwout  = (const float*)d_in[28];
    float* out = (float*)d_out;

    float *p_xn, *p_xz, *p_xs, *p_xdbl, *p_delta, *p_xm, *p_hbuf, *p_gg, *p_xmid;
    cudaGetSymbolAddress((void**)&p_xn,    g_xn);
    cudaGetSymbolAddress((void**)&p_xz,    g_xz);
    cudaGetSymbolAddress((void**)&p_xs,    g_xs);
    cudaGetSymbolAddress((void**)&p_xdbl,  g_xdbl);
    cudaGetSymbolAddress((void**)&p_delta, g_delta);
    cudaGetSymbolAddress((void**)&p_xm,    g_xm);
    cudaGetSymbolAddress((void**)&p_hbuf,  g_hbuf);
    cudaGetSymbolAddress((void**)&p_gg,    g_gg);
    cudaGetSymbolAddress((void**)&p_xmid,  g_xmid);

    const long DIRD = (long)BD * LD * DI;

    const int SM_G96  = (48 * (2 * 64 + 8) + 48 * 72) * 4;   // ~39.9 KB (bf16 packed)
    const int SM_G192 = (96 * (1 * 64 + 8) + 96 * 72) * 4;   // ~55.3 KB (bf16 packed)
    const int SM_XDBL = (192 * 72 + 192 * 40) * 4 + (64 * 8 + 192 * 6 + 192) * 4;  // ~93 KB (tf32)

    cudaFuncSetAttribute((const void*)gemm_fk<2, 96, true, 0>,
                         cudaFuncAttributeMaxDynamicSharedMemorySize, SM_G96);
    cudaFuncSetAttribute((const void*)gemm_fk<1, 192, false, 1>,
                         cudaFuncAttributeMaxDynamicSharedMemorySize, SM_G192);
    cudaFuncSetAttribute((const void*)xdbl_delta_k,
                         cudaFuncAttributeMaxDynamicSharedMemorySize, SM_XDBL);

    // 0. double LN (256 blocks)
    ln_double_k<<<256, 256>>>(x, ln1w, ln1b, mnw, mnb);

    // 1. xz = xn @ Win^T  M=8192 N=384 K=96 (768 blocks, bf16)
    gemm_fk<2, 96, true, 0><<<dim3(6, 64, 2), 256, SM_G96>>>(
        p_xn, Win[0], Win[1], p_xz, BD * LD, 384,
        0, 0, (long)BD * LD * 384, nullptr, nullptr, 0);

    // 2. conv + silu (256 blocks)
    conv_silu_k<<<256, 192>>>(convw[0], convb[0], convw[1], convb[1]);

    // 3. x_dbl GEMM + fused delta (256 blocks, tf32 proven-best)  <-- ncu slot
    xdbl_delta_k<<<dim3(1, 128, 2), 256, SM_XDBL>>>(
        p_xs, Wx[0], Wx[1], p_xdbl, Wdt[0], Wdt[1], bdt[0], bdt[1],
        p_delta, p_delta + DIRD);

    // 4. scan p1 (256 blocks)
    scan_p1<<<256, 192>>>(Alog[0], Alog[1]);

    // 5. scan p2 (96 blocks x 128)
    scan_p2<<<dim3(24, BD, 2), 128>>>(Alog[0], Alog[1]);

    // 6. scan p3 both dirs (256 blocks)
    scan_p3<<<256, 192>>>(Alog[0], Alog[1], Dp[0], Dp[1]);

    // 7. yo GEMM + resid1 + channel LN fused (256 blocks, bf16)
    yo_ln_k<<<256, 256>>>(Wout, x, gamma1, ln1w, ln1b);

    // 8. h = msff_win @ xm^T  M=576 N=4096 K=96 (640 blocks, bf16)
    gemm_fk<2, 96, true, 0><<<dim3(64, 5, 2), 256, SM_G96>>>(
        mwin, p_xm, nullptr, p_hbuf, 3 * HIDN, LD,
        0, (long)LD * CD, (long)3 * HIDN * LD, nullptr, nullptr, 0);

    // 9. gated multiscale dwconv (384 blocks)
    gate_k<<<384, 256>>>(dw1, dw2, dw3);

    // 10. out = xmid + gamma2*(msff_wout @ g)  M=96 N=4096 K=192 (256 blocks, bf16)
    gemm_fk<1, 192, false, 1><<<dim3(64, 2, 2), 256, SM_G192>>>(
        mwout, p_gg, nullptr, out, CD, LD,
        0, (long)HIDN * LD, (long)CD * LD, gamma2, p_xmid, (long)CD * LD);
}